// round 6
// baseline (speedup 1.0000x reference)
#include <cuda_runtime.h>
#include <cuda_fp16.h>
#include <float.h>

#define KDIM 256
#define NITER 50
#define NLOAD 512
#define NTH 544
#define BPC 4
#define NCHUNK 8
#define CHUNK_BYTES 32768        // 32 rows x 256 fp32
#define CHUNK_FLOATS 8192

// Shared memory layout (bytes)
#define CS_OFF   0               // 131072: 256 rows x 64 uint2 (fp16 M'), XOR-swizzled
#define STG_OFF  131072          // 65536: 2 x 32KB fp32 staging
#define FS_OFF   196608          // 2048: 2 x 256 floats f = 0.5*scores
#define GV_OFF   198656          // 2048: 2 x 256 floats row sums
#define WS_OFF   200704          // 64
#define WT_OFF   200768          // 64
#define WM_OFF   200832          // 64
#define CN_OFF   200896          // 32: 2 x {A, Bc, eps, Cc}
#define GT_OFF   200928          // 400: 50 x float2
#define IL_OFF   201344          // 256: FW idx list
#define GF_OFF   201600          // 1024: FW final g dump
#define MB_OFF   202624          // 16: two mbarriers
#define FL_OFF   202656          // 16
#define RB_OFF   202688          // 128
#define SMEM_BYTES 202816

__device__ float g_scratch[1024];
__device__ unsigned int g_count = 0;

__device__ __forceinline__ float ex2f(float x) {
    float y;
    asm("ex2.approx.ftz.f32 %0, %1;" : "=f"(y) : "f"(x));
    return y;
}
__device__ __forceinline__ void mbar_init(unsigned mbar, unsigned cnt) {
    asm volatile("mbarrier.init.shared::cta.b64 [%0], %1;" :: "r"(mbar), "r"(cnt) : "memory");
}
__device__ __forceinline__ void mbar_expect(unsigned mbar, unsigned bytes) {
    asm volatile("mbarrier.arrive.expect_tx.shared::cta.b64 _, [%0], %1;"
                 :: "r"(mbar), "r"(bytes) : "memory");
}
__device__ __forceinline__ void mbar_wait(unsigned mbar, unsigned phase) {
    asm volatile(
        "{\n\t"
        ".reg .pred P;\n\t"
        "LW_%=:\n\t"
        "mbarrier.try_wait.parity.shared::cta.b64 P, [%0], %1;\n\t"
        "@!P bra LW_%=;\n\t"
        "}\n"
        :: "r"(mbar), "r"(phase) : "memory");
}
__device__ __forceinline__ void tma_1d(unsigned dst, const void* src, unsigned bytes, unsigned mbar) {
    asm volatile(
        "cp.async.bulk.shared::cluster.global.mbarrier::complete_tx::bytes [%0], [%1], %2, [%3];"
        :: "r"(dst), "l"(src), "r"(bytes), "r"(mbar) : "memory");
}

// Frank-Wolfe, single warp. Packed-key argmin (1 REDUX/iter), PRMT half select,
// no alpha tracking (closed-form weights in epilogue).
__device__ __forceinline__ void run_fw(const uint2* __restrict__ Cs, const float* __restrict__ gvb,
                                       const float* __restrict__ consb, const float2* __restrict__ gtab,
                                       unsigned* __restrict__ idxl, float* __restrict__ gf,
                                       const float* __restrict__ scores, const int* __restrict__ targets,
                                       int b, int lane)
{
    float gr[8];
    unsigned rowc[8], rowb[8];
    #pragma unroll
    for (int m = 0; m < 8; m++) {
        rowc[m] = (unsigned)(lane + 32 * m);
        rowb[m] = rowc[m] * 64u;
        gr[m] = gvb[rowc[m]];
    }
    for (int it = 0; it < NITER; it++) {
        float2 gg = gtab[it];
        unsigned key = 0xffffffffu;
        #pragma unroll
        for (int m = 0; m < 8; m++)
            key = min(key, (__float_as_uint(gr[m]) & 0xffffff00u) | rowc[m]);
        unsigned kmin = __reduce_min_sync(0xffffffffu, key);
        unsigned idx = kmin & 0xffu;
        if (lane == 0) idxl[it] = idx;
        unsigned pw  = (idx >> 2) ^ (unsigned)lane;
        unsigned ctl = (idx & 3u) * 0x22u + 0x10u;
        #pragma unroll
        for (int m = 0; m < 8; m++) {
            uint2 u = Cs[rowb[m] + pw];
            unsigned hw = __byte_perm(u.x, u.y, ctl);
            float colv = __half2float(__ushort_as_half((unsigned short)hw));
            gr[m] = fmaf(gg.x, colv, gg.y * gr[m]);
        }
    }
    // epilogue: alpha_T = sum_t 2(t+1)/(T(T+1)) e_{idx_t}; dot = alpha . g_final
    #pragma unroll
    for (int m = 0; m < 8; m++) gf[rowc[m]] = gr[m];
    __syncwarp();
    float part = 0.f;
    if (lane < NITER)      part  = (float)(lane + 1)  * gf[idxl[lane]];
    if (lane + 32 < NITER) part += (float)(lane + 33) * gf[idxl[lane + 32]];
    #pragma unroll
    for (int o = 16; o; o >>= 1) part += __shfl_xor_sync(0xffffffffu, part, o);
    if (lane == 0) {
        float dot = part * (2.0f / (float)(NITER * (NITER + 1)));
        float conj = consb[3] - consb[2] * __logf(dot);
        g_scratch[b] = conj - scores[b * KDIM + targets[b]];
    }
}

extern "C" __global__ void __launch_bounds__(NTH, 1)
cacis_fused(const float* __restrict__ scores, const int* __restrict__ targets,
            const float* __restrict__ C, float* __restrict__ out, int B)
{
    extern __shared__ unsigned char smraw[];
    uint2*    Cs   = (uint2*)(smraw + CS_OFF);
    float*    fsb  = (float*)(smraw + FS_OFF);
    float*    gvb  = (float*)(smraw + GV_OFF);
    float*    wsum = (float*)(smraw + WS_OFF);
    float*    wtr  = (float*)(smraw + WT_OFF);
    float*    wmin = (float*)(smraw + WM_OFF);
    float*    cons = (float*)(smraw + CN_OFF);
    float2*   gtab = (float2*)(smraw + GT_OFF);
    unsigned* idxl = (unsigned*)(smraw + IL_OFF);
    float*    gf   = (float*)(smraw + GF_OFF);
    int*      flg  = (int*)(smraw + FL_OFF);
    float*    rbuf = (float*)(smraw + RB_OFF);

    const unsigned smem_base = (unsigned)__cvta_generic_to_shared(smraw);
    const unsigned stg_a[2] = { smem_base + STG_OFF, smem_base + STG_OFF + CHUNK_BYTES };
    const unsigned mb_a[2]  = { smem_base + MB_OFF, smem_base + MB_OFF + 8 };

    const int t = threadIdx.x, lane = t & 31, wid = t >> 5;
    const int b0 = blockIdx.x * BPC;
    const int nb = min(BPC, B - b0);
    const float* Cbase = C + (size_t)b0 * (KDIM * KDIM);

    const int rl0 = t >> 4;          // loader row-in-chunk (0..31)
    const int cl0 = t & 15;          // loader col4 base

    unsigned cdat[64];
    unsigned ph0 = 0, ph1 = 0;

    // ---- prologue ----
    if (t == 0) { mbar_init(mb_a[0], 1); mbar_init(mb_a[1], 1); }
    if (t < KDIM) fsb[t] = 0.5f * scores[b0 * KDIM + t];
    if (t < NITER) { float g = 2.0f / (float)(t + 2); gtab[t] = make_float2(g, 1.0f - g); }
    __syncthreads();
    if (t == 0) {
        mbar_expect(mb_a[0], CHUNK_BYTES); tma_1d(stg_a[0], Cbase, CHUNK_BYTES, mb_a[0]);
        mbar_expect(mb_a[1], CHUNK_BYTES); tma_1d(stg_a[1], Cbase + CHUNK_FLOATS, CHUNK_BYTES, mb_a[1]);
    }

    for (int k = 0; k <= nb; k++) {
        const int cur = k & 1;
        // ================= P1: [FW(k-1) on warp16] || [load batch k into regs] =================
        if (wid == 16) {
            if (k < nb) {
                #pragma unroll
                for (int i = lane; i < KDIM; i += 32) gvb[cur * KDIM + i] = 0.f;
            }
            if (k >= 1) {
                const int p = (k - 1) & 1;
                run_fw(Cs, gvb + p * KDIM, cons + p * 4, gtab, idxl, gf,
                       scores, targets, b0 + k - 1, lane);
            }
        } else if (k < nb) {
            const float*  fsC  = fsb + cur * KDIM;
            const float4* fsC4 = (const float4*)fsC;
            float psum = 0.f, ptrc = 0.f, pmin = FLT_MAX;
            #pragma unroll
            for (int c = 0; c < NCHUNK; c++) {
                const int bi = c & 1;
                if (bi == 0) { mbar_wait(mb_a[0], ph0); ph0 ^= 1; }
                else         { mbar_wait(mb_a[1], ph1); ph1 ^= 1; }
                const float4* stg = (const float4*)(smraw + STG_OFF + bi * CHUNK_BYTES);
                const int r = c * 32 + rl0;
                const float fi = fsC[r];
                #pragma unroll
                for (int kk = 0; kk < 4; kk++) {
                    const int c4 = cl0 + 16 * kk;
                    float4 cc = stg[rl0 * 64 + c4];
                    float4 fj = fsC4[c4];
                    float v0 = fminf(fj.x + cc.x, fj.y + cc.y);
                    float v1 = fminf(fj.z + cc.z, fj.w + cc.w);
                    pmin = fminf(pmin, fi + fminf(v0, v1));
                    psum += (cc.x + cc.y) + (cc.z + cc.w);
                    const int d = r - 4 * c4;
                    if ((unsigned)d < 4u)
                        ptrc += (d == 0) ? cc.x : (d == 1) ? cc.y : (d == 2) ? cc.z : cc.w;
                    __half2 h01 = __floats2half2_rn(cc.x, cc.y);
                    __half2 h23 = __floats2half2_rn(cc.z, cc.w);
                    cdat[c * 8 + kk * 2]     = *(unsigned*)&h01;
                    cdat[c * 8 + kk * 2 + 1] = *(unsigned*)&h23;
                }
                asm volatile("bar.sync 1, %0;" :: "n"(NLOAD) : "memory");
                if (t == 0) {
                    const int s = k * NCHUNK + c + 2;
                    if (s < nb * NCHUNK) {
                        mbar_expect(mb_a[bi], CHUNK_BYTES);
                        tma_1d(stg_a[bi], Cbase + (size_t)s * CHUNK_FLOATS, CHUNK_BYTES, mb_a[bi]);
                    }
                }
            }
            #pragma unroll
            for (int o = 16; o; o >>= 1) {
                psum += __shfl_down_sync(0xffffffffu, psum, o);
                ptrc += __shfl_down_sync(0xffffffffu, ptrc, o);
                pmin  = fminf(pmin, __shfl_down_sync(0xffffffffu, pmin, o));
            }
            if (lane == 0) { wsum[wid] = psum; wtr[wid] = ptrc; wmin[wid] = pmin; }
        }
        __syncthreads();
        if (k == nb) break;

        // ================= P2: transform regs -> M' (fp16) in Cs, row sums =================
        if (wid == 16) {
            if (t == NLOAD) {        // finalize + publish cons[cur] for FW
                float s = 0.f, tr = 0.f, mn = FLT_MAX;
                #pragma unroll
                for (int w = 0; w < 16; w++) { s += wsum[w]; tr += wtr[w]; mn = fminf(mn, wmin[w]); }
                float eps = fmaxf((s - tr) / 65280.0f, 1e-8f);
                float k2 = 1.4426950408889634f / eps;
                cons[cur * 4 + 0] = -k2;
                cons[cur * 4 + 1] = fmaf(mn, k2, 14.0f);
                cons[cur * 4 + 2] = eps;
                cons[cur * 4 + 3] = fmaf(9.7040605278392342f, eps, mn);
            }
            if (k + 1 < nb) {
                const int nxt = (k + 1) & 1;
                #pragma unroll
                for (int i = lane; i < KDIM; i += 32)
                    fsb[nxt * KDIM + i] = 0.5f * scores[(b0 + k + 1) * KDIM + i];
            }
        } else {
            // each loader recomputes A, Bc locally (no extra barrier needed)
            float s = 0.f, tr = 0.f, mn = FLT_MAX;
            #pragma unroll
            for (int w = 0; w < 16; w++) { s += wsum[w]; tr += wtr[w]; mn = fminf(mn, wmin[w]); }
            float eps = fmaxf((s - tr) / 65280.0f, 1e-8f);
            float k2 = 1.4426950408889634f / eps;
            const float A = -k2;
            const float Bc = fmaf(mn, k2, 14.0f);

            const float*  fsC  = fsb + cur * KDIM;
            const float4* fsC4 = (const float4*)fsC;
            float* gvc = gvb + cur * KDIM;
            #pragma unroll
            for (int c = 0; c < NCHUNK; c++) {
                const int r = c * 32 + rl0;
                const float fiA = fsC[r] * A;
                float rs = 0.f;
                #pragma unroll
                for (int kk = 0; kk < 4; kk++) {
                    const int c4 = cl0 + 16 * kk;
                    float4 fj = fsC4[c4];
                    float2 c01 = __half22float2(*(__half2*)&cdat[c * 8 + kk * 2]);
                    float2 c23 = __half22float2(*(__half2*)&cdat[c * 8 + kk * 2 + 1]);
                    float m0 = ex2f(fmaf(c01.x, A, fiA + fmaf(fj.x, A, Bc)));
                    float m1 = ex2f(fmaf(c01.y, A, fiA + fmaf(fj.y, A, Bc)));
                    float m2 = ex2f(fmaf(c23.x, A, fiA + fmaf(fj.z, A, Bc)));
                    float m3 = ex2f(fmaf(c23.y, A, fiA + fmaf(fj.w, A, Bc)));
                    rs += (m0 + m1) + (m2 + m3);
                    __half2 o01 = __floats2half2_rn(m0, m1);
                    __half2 o23 = __floats2half2_rn(m2, m3);
                    uint2 st;
                    st.x = *(unsigned*)&o01;
                    st.y = *(unsigned*)&o23;
                    Cs[r * 64 + (c4 ^ rl0)] = st;
                }
                // 16 threads share row r: half-warp reduce, single writer per row
                rs += __shfl_xor_sync(0xffffffffu, rs, 8);
                rs += __shfl_xor_sync(0xffffffffu, rs, 4);
                rs += __shfl_xor_sync(0xffffffffu, rs, 2);
                rs += __shfl_xor_sync(0xffffffffu, rs, 1);
                if ((lane & 15) == 0) gvc[r] = rs;
            }
        }
        __syncthreads();
    }

    // ---- fused cross-CTA reduction: last CTA sums g_scratch in fixed order ----
    if (t == 0) {
        __threadfence();
        unsigned prev = atomicAdd(&g_count, 1u);
        *flg = (prev == gridDim.x - 1) ? 1 : 0;
    }
    __syncthreads();
    if (*flg) {
        if (t == 0) g_count = 0;                   // reset for next graph replay
        __threadfence();
        float s = 0.f;
        for (int i = t; i < B; i += NTH) s += __ldcg(&g_scratch[i]);
        #pragma unroll
        for (int o = 16; o; o >>= 1) s += __shfl_down_sync(0xffffffffu, s, o);
        if (lane == 0) rbuf[wid] = s;
        __syncthreads();
        if (t == 0) {
            float tot = 0.f;
            #pragma unroll
            for (int w = 0; w < 17; w++) tot += rbuf[w];
            out[0] = tot / (float)B;
        }
    }
}

extern "C" void kernel_launch(void* const* d_in, const int* in_sizes, int n_in,
                              void* d_out, int out_size)
{
    const float* scores  = (const float*)d_in[0];
    const int*   targets = (const int*)d_in[1];
    const float* C       = (const float*)d_in[2];
    const int B = in_sizes[1];
    const int grid = (B + BPC - 1) / BPC;

    cudaFuncSetAttribute(cacis_fused, cudaFuncAttributeMaxDynamicSharedMemorySize, SMEM_BYTES);
    cacis_fused<<<grid, NTH, SMEM_BYTES>>>(scores, targets, C, (float*)d_out, B);
}

// round 10
// speedup vs baseline: 1.3667x; 1.3667x over previous
#include <cuda_runtime.h>
#include <cuda_fp16.h>
#include <float.h>

#define KDIM 256
#define NITER 50
#define NTH 512
#define BPC 4
#define NBUF 5
#define NCHUNK 16                // chunks per batch
#define CHUNK_BYTES 16384        // 16 rows x 256 fp32
#define CHUNK_FLOATS 4096

// Shared memory layout (bytes) — total 215808, well under 232448 opt-in cap
#define CS_OFF   0               // 131072: 256 rows x 64 uint2 (fp16), XOR-swizzled
#define STG_OFF  131072          // 81920: 5 x 16KB fp32 staging ring
#define FS_OFF   212992          // 1024: f = 0.5*scores
#define GV_OFF   214016          // 1024: row sums
#define WS_OFF   215040          // 64
#define WT_OFF   215104          // 64
#define WM_OFF   215168          // 64
#define CN_OFF   215232          // 32: A, Bc, eps, Cc
#define GT_OFF   215264          // 400: 50 x float2
#define MB_OFF   215664          // 40: 5 mbarriers
#define FL_OFF   215704          // 16
#define RB_OFF   215720          // 64+
#define SMEM_BYTES 215808

__device__ float g_scratch[1024];
__device__ unsigned int g_count = 0;

__device__ __forceinline__ float ex2f(float x) {
    float y;
    asm("ex2.approx.ftz.f32 %0, %1;" : "=f"(y) : "f"(x));
    return y;
}
__device__ __forceinline__ void mbar_init(unsigned mbar, unsigned cnt) {
    asm volatile("mbarrier.init.shared::cta.b64 [%0], %1;" :: "r"(mbar), "r"(cnt) : "memory");
}
__device__ __forceinline__ void mbar_expect(unsigned mbar, unsigned bytes) {
    asm volatile("mbarrier.arrive.expect_tx.shared::cta.b64 _, [%0], %1;"
                 :: "r"(mbar), "r"(bytes) : "memory");
}
__device__ __forceinline__ void mbar_wait(unsigned mbar, unsigned phase) {
    asm volatile(
        "{\n\t"
        ".reg .pred P;\n\t"
        "LW_%=:\n\t"
        "mbarrier.try_wait.parity.shared::cta.b64 P, [%0], %1;\n\t"
        "@!P bra LW_%=;\n\t"
        "}\n"
        :: "r"(mbar), "r"(phase) : "memory");
}
__device__ __forceinline__ void tma_1d(unsigned dst, const void* src, unsigned bytes, unsigned mbar) {
    asm volatile(
        "cp.async.bulk.shared::cluster.global.mbarrier::complete_tx::bytes [%0], [%1], %2, [%3];"
        :: "r"(dst), "l"(src), "r"(bytes), "r"(mbar) : "memory");
}

// Frank-Wolfe: single warp, packed-key argmin (1 REDUX/iter), PRMT half select,
// conflict-free LDS.64 column gather.
__device__ __forceinline__ void run_fw(const uint2* __restrict__ Cs, const float* __restrict__ gv,
                                       const float* __restrict__ cons, const float2* __restrict__ gtab,
                                       const float* __restrict__ scores, const int* __restrict__ targets,
                                       int b, int lane)
{
    float gr[8], al[8];
    #pragma unroll
    for (int m = 0; m < 8; m++) { gr[m] = gv[lane + 32 * m]; al[m] = 0.00390625f; }
    for (int it = 0; it < NITER; it++) {
        float2 gg = gtab[it];
        unsigned key = 0xffffffffu;
        #pragma unroll
        for (int m = 0; m < 8; m++)
            key = min(key, (__float_as_uint(gr[m]) & 0xffffff00u) | (unsigned)(lane + 32 * m));
        unsigned kmin = __reduce_min_sync(0xffffffffu, key);
        unsigned idx = kmin & 0xffu;
        unsigned pw  = (idx >> 2) ^ (unsigned)lane;
        unsigned ctl = (idx & 3u) * 0x22u + 0x10u;
        #pragma unroll
        for (int m = 0; m < 8; m++) {
            unsigned row = (unsigned)lane + 32u * m;
            uint2 u = Cs[row * 64u + pw];
            unsigned hw = __byte_perm(u.x, u.y, ctl);
            float colv = __half2float(__ushort_as_half((unsigned short)hw));
            gr[m] = fmaf(gg.x, colv, gg.y * gr[m]);
            al[m] = fmaf(gg.y, al[m], (row == idx) ? gg.x : 0.0f);
        }
    }
    float dot = 0.f;
    #pragma unroll
    for (int m = 0; m < 8; m++) dot = fmaf(al[m], gr[m], dot);
    #pragma unroll
    for (int o = 16; o; o >>= 1) dot += __shfl_xor_sync(0xffffffffu, dot, o);
    if (lane == 0) {
        float conj = cons[3] - cons[2] * __logf(dot);
        g_scratch[b] = conj - scores[b * KDIM + targets[b]];
    }
}

extern "C" __global__ void __launch_bounds__(NTH, 1)
cacis_fused(const float* __restrict__ scores, const int* __restrict__ targets,
            const float* __restrict__ C, float* __restrict__ out, int B)
{
    extern __shared__ unsigned char smraw[];
    uint2*  Cs   = (uint2*)(smraw + CS_OFF);
    float*  fs   = (float*)(smraw + FS_OFF);
    float*  gv   = (float*)(smraw + GV_OFF);
    float*  wsum = (float*)(smraw + WS_OFF);
    float*  wtr  = (float*)(smraw + WT_OFF);
    float*  wmin = (float*)(smraw + WM_OFF);
    float*  cons = (float*)(smraw + CN_OFF);
    float2* gtab = (float2*)(smraw + GT_OFF);
    int*    flg  = (int*)(smraw + FL_OFF);
    float*  rbuf = (float*)(smraw + RB_OFF);
    const float4* fs4 = (const float4*)fs;

    const unsigned smem_base = (unsigned)__cvta_generic_to_shared(smraw);
    const unsigned stgB = smem_base + STG_OFF;
    const unsigned mbB  = smem_base + MB_OFF;

    const int t = threadIdx.x, lane = t & 31, wid = t >> 5;
    const int b0 = blockIdx.x * BPC;
    const int nb = min(BPC, B - b0);
    const int total = nb * NCHUNK;
    const float* Cbase = C + (size_t)b0 * (KDIM * KDIM);

    // ---- prologue ----
    if (t == 0) {
        #pragma unroll
        for (int i = 0; i < NBUF; i++) mbar_init(mbB + 8u * i, 1);
    }
    if (t < KDIM) fs[t] = 0.5f * scores[b0 * KDIM + t];
    if (t < NITER) { float g = 2.0f / (float)(t + 2); gtab[t] = make_float2(g, 1.0f - g); }
    __syncthreads();
    if (t == 0) {
        #pragma unroll
        for (int s = 0; s < NBUF; s++) {
            if (s < total) {
                mbar_expect(mbB + 8u * s, CHUNK_BYTES);
                tma_1d(stgB + s * CHUNK_BYTES, Cbase + (size_t)s * CHUNK_FLOATS, CHUNK_BYTES, mbB + 8u * s);
            }
        }
    }

    int bi = 0;                    // staging ring cursor (consumer order)
    unsigned phmask = 0;           // per-buffer parity bits

    for (int k = 0; k < nb; k++) {
        // ================= convert: TMA fp32 chunks -> reductions + fp16 C in Cs =================
        float psum = 0.f, ptrc = 0.f, pmin = FLT_MAX;
        {
            const int rl = wid;                      // warp owns one row per chunk
            const float4 fj0 = fs4[lane];
            const float4 fj1 = fs4[lane + 32];
            const int c40 = lane, c41 = lane + 32;
            #pragma unroll
            for (int c = 0; c < NCHUNK; c++) {
                const unsigned mb = mbB + 8u * bi;
                mbar_wait(mb, (phmask >> bi) & 1u);
                phmask ^= 1u << bi;
                const float4* stg = (const float4*)(smraw + STG_OFF + bi * CHUNK_BYTES);
                const int r = c * 16 + rl;
                const float fi = fs[r];
                float4 cc0 = stg[rl * 64 + c40];
                float4 cc1 = stg[rl * 64 + c41];

                float v0 = fminf(fj0.x + cc0.x, fj0.y + cc0.y);
                float v1 = fminf(fj0.z + cc0.z, fj0.w + cc0.w);
                float v2 = fminf(fj1.x + cc1.x, fj1.y + cc1.y);
                float v3 = fminf(fj1.z + cc1.z, fj1.w + cc1.w);
                pmin = fminf(pmin, fi + fminf(fminf(v0, v1), fminf(v2, v3)));
                psum += ((cc0.x + cc0.y) + (cc0.z + cc0.w)) + ((cc1.x + cc1.y) + (cc1.z + cc1.w));
                int d0 = r - 4 * c40;
                if ((unsigned)d0 < 4u)
                    ptrc += (d0 == 0) ? cc0.x : (d0 == 1) ? cc0.y : (d0 == 2) ? cc0.z : cc0.w;
                int d1 = r - 4 * c41;
                if ((unsigned)d1 < 4u)
                    ptrc += (d1 == 0) ? cc1.x : (d1 == 1) ? cc1.y : (d1 == 2) ? cc1.z : cc1.w;

                __half2 h00 = __floats2half2_rn(cc0.x, cc0.y);
                __half2 h01 = __floats2half2_rn(cc0.z, cc0.w);
                __half2 h10 = __floats2half2_rn(cc1.x, cc1.y);
                __half2 h11 = __floats2half2_rn(cc1.z, cc1.w);
                uint2 s0, s1;
                s0.x = *(unsigned*)&h00; s0.y = *(unsigned*)&h01;
                s1.x = *(unsigned*)&h10; s1.y = *(unsigned*)&h11;
                const int sw = r & 31;
                Cs[r * 64 + (c40 ^ sw)] = s0;
                Cs[r * 64 + (c41 ^ sw)] = s1;

                __syncthreads();                      // buffer bi fully consumed
                if (t == 0) {
                    const int s = k * NCHUNK + c + NBUF;   // continuous stream across batches
                    if (s < total) {
                        mbar_expect(mb, CHUNK_BYTES);
                        tma_1d(stgB + bi * CHUNK_BYTES, Cbase + (size_t)s * CHUNK_FLOATS, CHUNK_BYTES, mb);
                    }
                }
                bi = (bi + 1 == NBUF) ? 0 : bi + 1;
            }
        }
        #pragma unroll
        for (int o = 16; o; o >>= 1) {
            psum += __shfl_down_sync(0xffffffffu, psum, o);
            ptrc += __shfl_down_sync(0xffffffffu, ptrc, o);
            pmin  = fminf(pmin, __shfl_down_sync(0xffffffffu, pmin, o));
        }
        if (lane == 0) { wsum[wid] = psum; wtr[wid] = ptrc; wmin[wid] = pmin; }
        __syncthreads();

        if (t == 0) {
            float s = 0.f, tr = 0.f, mn = FLT_MAX;
            #pragma unroll
            for (int w = 0; w < 16; w++) { s += wsum[w]; tr += wtr[w]; mn = fminf(mn, wmin[w]); }
            float eps = fmaxf((s - tr) / 65280.0f, 1e-8f);      // K*K-K
            float k2 = 1.4426950408889634f / eps;               // log2(e)/eps
            cons[0] = -k2;                                      // A
            cons[1] = fmaf(mn, k2, 14.0f);                      // Bc: M' = M * 2^14
            cons[2] = eps;
            cons[3] = fmaf(9.7040605278392342f, eps, mn);       // Cc = mn + 14*ln2*eps
        }
        if (t < KDIM) gv[t] = 0.0f;
        __syncthreads();

        // ================= transform: Cs fp16 C -> fp16 M' = 2^((mn-num)*k + 14), row sums =================
        {
            const float A = cons[0], Bc = cons[1];
            const int i = t & 255, hh = t >> 8, sw = i & 31;
            uint2* rowp = Cs + i * 64;
            const float fiAB = fmaf(fs[i], A, Bc);
            float rs = 0.f;
            #pragma unroll 8
            for (int ww = hh * 32; ww < hh * 32 + 32; ww++) {
                const int pa = ww ^ sw;
                uint2 uu = rowp[pa];
                float2 c01 = __half22float2(*(__half2*)&uu.x);
                float2 c23 = __half22float2(*(__half2*)&uu.y);
                float4 fj = fs4[ww];
                float m0 = ex2f(fmaf(c01.x, A, fmaf(fj.x, A, fiAB)));
                float m1 = ex2f(fmaf(c01.y, A, fmaf(fj.y, A, fiAB)));
                float m2 = ex2f(fmaf(c23.x, A, fmaf(fj.z, A, fiAB)));
                float m3 = ex2f(fmaf(c23.y, A, fmaf(fj.w, A, fiAB)));
                rs += (m0 + m1) + (m2 + m3);
                __half2 o01 = __floats2half2_rn(m0, m1);
                __half2 o23 = __floats2half2_rn(m2, m3);
                uint2 st;
                st.x = *(unsigned*)&o01;
                st.y = *(unsigned*)&o23;
                rowp[pa] = st;
            }
            atomicAdd(&gv[i], rs);                    // exactly 2 commutative adds per row
        }
        __syncthreads();

        // ================= FW (warp 0) || fs prefetch for next batch (warps 8-15) =================
        if (wid == 0) {
            run_fw(Cs, gv, cons, gtab, scores, targets, b0 + k, lane);
        } else if (t >= 256 && k + 1 < nb) {
            fs[t - 256] = 0.5f * scores[(b0 + k + 1) * KDIM + (t - 256)];
        }
        __syncthreads();
    }

    // ---- fused cross-CTA reduction: last CTA sums g_scratch in fixed order ----
    if (t == 0) {
        __threadfence();
        unsigned prev = atomicAdd(&g_count, 1u);
        *flg = (prev == gridDim.x - 1) ? 1 : 0;
    }
    __syncthreads();
    if (*flg) {
        if (t == 0) g_count = 0;                      // reset for next graph replay
        __threadfence();
        float s = 0.f;
        for (int i = t; i < B; i += NTH) s += __ldcg(&g_scratch[i]);
        #pragma unroll
        for (int o = 16; o; o >>= 1) s += __shfl_down_sync(0xffffffffu, s, o);
        if (lane == 0) rbuf[wid] = s;
        __syncthreads();
        if (t == 0) {
            float tot = 0.f;
            #pragma unroll
            for (int w = 0; w < 16; w++) tot += rbuf[w];
            out[0] = tot / (float)B;
        }
    }
}

extern "C" void kernel_launch(void* const* d_in, const int* in_sizes, int n_in,
                              void* d_out, int out_size)
{
    const float* scores  = (const float*)d_in[0];
    const int*   targets = (const int*)d_in[1];
    const float* C       = (const float*)d_in[2];
    const int B = in_sizes[1];
    const int grid = (B + BPC - 1) / BPC;

    cudaFuncSetAttribute(cacis_fused, cudaFuncAttributeMaxDynamicSharedMemorySize, SMEM_BYTES);
    cacis_fused<<<grid, NTH, SMEM_BYTES>>>(scores, targets, C, (float*)d_out, B);
}